// round 17
// baseline (speedup 1.0000x reference)
#include <cuda_runtime.h>
#include <math.h>

#define FULLMASK 0xffffffffu
#define KSEL   9
#define WARPS  8
#define TPB    256
#define NBX    16            /* 16x16 spatial bins */
#define NBINS  (NBX * NBX)
#define MAXN   32768

#define INFKEY ((0x7f800000ULL << 32) | 0x7fffffffULL)

// ---------------- scratch (device globals; no allocation allowed) ----------
__device__ float2 g_slocs [MAXN];      // bin-sorted locations
__device__ int    g_sidx  [MAXN];      // original indices
__device__ int    g_binOff[NBINS + 1];
__device__ float  g_part_focal[4096];  // per-TILE partials (tile-keyed => deterministic)
__device__ float  g_part_bbox [4096];
__device__ float  g_part_giou [4096];
__device__ float  g_part_delta[4096];
__device__ int    g_tile    = 0;       // focal work-steal counter
__device__ int    g_bindone = 0;       // binning-complete flag
__device__ int    g_ctr     = 0;       // finalize ticket

// ---------------- packed f32x2 helpers --------------------------------------
__device__ __forceinline__ unsigned long long pk2(float lo, float hi) {
    unsigned long long r;
    asm("mov.b64 %0, {%1, %2};" : "=l"(r) : "f"(lo), "f"(hi));
    return r;
}
__device__ __forceinline__ void upk2(unsigned long long v, float& lo, float& hi) {
    asm("mov.b64 {%0, %1}, %2;" : "=f"(lo), "=f"(hi) : "l"(v));
}
__device__ __forceinline__ unsigned long long fma2_(unsigned long long a,
                                                    unsigned long long b,
                                                    unsigned long long c) {
    unsigned long long d;
    asm("fma.rn.f32x2 %0, %1, %2, %3;" : "=l"(d) : "l"(a), "l"(b), "l"(c));
    return d;
}
__device__ __forceinline__ unsigned long long mul2_(unsigned long long a,
                                                    unsigned long long b) {
    unsigned long long d;
    asm("mul.rn.f32x2 %0, %1, %2;" : "=l"(d) : "l"(a), "l"(b));
    return d;
}
__device__ __forceinline__ unsigned long long add2_(unsigned long long a,
                                                    unsigned long long b) {
    unsigned long long d;
    asm("add.rn.f32x2 %0, %1, %2;" : "=l"(d) : "l"(a), "l"(b));
    return d;
}
__device__ __forceinline__ unsigned long long dup2(float c) {
    unsigned u = __float_as_uint(c);
    return ((unsigned long long)u << 32) | (unsigned long long)u;
}

// ---------------- focal pieces ---------------------------------------------
__device__ __forceinline__ float focal_t0(float x) {
    float ax   = fabsf(x);
    float u    = __expf(-ax);
    float r    = __fdividef(1.0f, 1.0f + u);
    float prob = (x >= 0.0f) ? r : (1.0f - r);
    float sp   = fmaxf(x, 0.0f) + __logf(1.0f + u);
    return 0.75f * sp * (prob * prob);
}
__device__ __forceinline__ float focal_t1(float x) {
    float ax   = fabsf(x);
    float u    = __expf(-ax);
    float r    = __fdividef(1.0f, 1.0f + u);
    float prob = (x >= 0.0f) ? r : (1.0f - r);
    float q    = 1.0f - prob;
    float spn  = fmaxf(-x, 0.0f) + __logf(1.0f + u);
    return 0.25f * spn * (q * q);
}

// 2-element focal_t0 core: 4 MUFU + packed-f32x2 degree-5 minimax log1p
// (A&S 4.1.43, |eps| <= 1e-5 abs on [0,1]; contributes ~1e-5 rel to loss_cls).
__device__ __forceinline__ void fpair(float x0, float x1, unsigned long long& ACC) {
    float u0 = __expf(-fabsf(x0));
    float u1 = __expf(-fabsf(x1));
    float r0 = __fdividef(1.0f, 1.0f + u0);
    float r1 = __fdividef(1.0f, 1.0f + u1);
    unsigned long long U = pk2(u0, u1);
    unsigned long long t = fma2_(U, dup2( 0.03215845f), dup2(-0.13606275f));
    t = fma2_(t, U, dup2( 0.28947478f));
    t = fma2_(t, U, dup2(-0.49190896f));
    t = fma2_(t, U, dup2( 0.99949556f));
    unsigned long long LG = mul2_(t, U);                 // log1p(u)
    unsigned long long SP = add2_(pk2(fmaxf(x0, 0.0f), fmaxf(x1, 0.0f)), LG);
    float p0 = (x0 >= 0.0f) ? r0 : (1.0f - r0);
    float p1 = (x1 >= 0.0f) ? r1 : (1.0f - r1);
    unsigned long long PR = pk2(p0, p1);
    ACC = fma2_(SP, mul2_(PR, PR), ACC);
}
__device__ __forceinline__ void focal4(float4 f, unsigned long long& ACC) {
    fpair(f.x, f.y, ACC);
    fpair(f.z, f.w, ACC);
}

// ---------------- top-9 helpers ---------------------------------------------
__device__ __forceinline__ void insert9(float (&dk)[KSEL], int (&ik)[KSEL],
                                        float d, int idx) {
    if (d < dk[KSEL - 1]) {
        dk[KSEL - 1] = d; ik[KSEL - 1] = idx;
#pragma unroll
        for (int j = KSEL - 1; j > 0; --j) {
            if (dk[j] < dk[j - 1]) {
                float td = dk[j]; dk[j] = dk[j - 1]; dk[j - 1] = td;
                int   ti = ik[j]; ik[j] = ik[j - 1]; ik[j - 1] = ti;
            }
        }
    }
}

__device__ __forceinline__ unsigned long long
warp_merge9(float (&dk)[KSEL], int (&ik)[KSEL], int lane) {
    unsigned long long mykey = INFKEY;
    unsigned long long key =
        (((unsigned long long)__float_as_uint(dk[0])) << 32) | (unsigned)ik[0];
#pragma unroll
    for (int r = 0; r < KSEL; ++r) {
        unsigned long long k = key;
#pragma unroll
        for (int off = 16; off > 0; off >>= 1) {
            unsigned long long o = __shfl_xor_sync(FULLMASK, k, off);
            k = (o < k) ? o : k;
        }
        if (lane == r) mykey = k;
        if (key == k) {
#pragma unroll
            for (int j = 0; j < KSEL - 1; ++j) { dk[j] = dk[j + 1]; ik[j] = ik[j + 1]; }
            dk[KSEL - 1] = __int_as_float(0x7f800000);
            ik[KSEL - 1] = 0x7fffffff;
            key = (((unsigned long long)__float_as_uint(dk[0])) << 32) | (unsigned)ik[0];
        }
    }
    return mykey;
}

// ---------------- THE kernel: bin -> pairs -> focal steal -> finalize -------
__global__ void __launch_bounds__(TPB, 6)
mega_kernel(const float*  __restrict__ logits,
            const float4* __restrict__ pred_boxes,
            const float2* __restrict__ locs,
            const float4* __restrict__ gt_boxes,
            const int*    __restrict__ gt_labels,
            float* __restrict__ out,
            int B, int N, int C, int G, int MB,
            int n8f, int total, int NT, int tileUnits,
            double invBNC, double invBB, double invGI)
{
    __shared__ __align__(16) union {
        struct { int bcnt[NBINS]; int boff[NBINS + 1]; } bin;
        float  red[32];
        double dred[3][TPB];
    } sm;
    __shared__ int stile;
    __shared__ int sticket;

    const int tid  = threadIdx.x;
    const int lane = tid & 31;
    const int warp = tid >> 5;
    const int bid  = blockIdx.x;
    const int P    = B * G;
    const float INF = __int_as_float(0x7f800000);

    // ================= role 0 (block 0): spatial binning ======================
    if (bid == 0) {
        for (int i = tid; i < NBINS; i += TPB) sm.bin.bcnt[i] = 0;
        __syncthreads();
        for (int i = tid; i < N; i += TPB) {
            float2 L = locs[i];
            int bx = min(NBX - 1, (int)(L.x * (float)NBX));
            int by = min(NBX - 1, (int)(L.y * (float)NBX));
            atomicAdd(&sm.bin.bcnt[by * NBX + bx], 1);
        }
        __syncthreads();
        if (tid == 0) {
            int s = 0;
            for (int b = 0; b < NBINS; ++b) { sm.bin.boff[b] = s; s += sm.bin.bcnt[b]; }
            sm.bin.boff[NBINS] = s;
        }
        __syncthreads();
        for (int i = tid; i < NBINS + 1; i += TPB) g_binOff[i] = sm.bin.boff[i];
        for (int i = tid; i < NBINS; i += TPB) sm.bin.bcnt[i] = 0;   // reuse as cursors
        __syncthreads();
        for (int i = tid; i < N; i += TPB) {
            float2 L = locs[i];
            int bx = min(NBX - 1, (int)(L.x * (float)NBX));
            int by = min(NBX - 1, (int)(L.y * (float)NBX));
            int b  = by * NBX + bx;
            int pos = sm.bin.boff[b] + atomicAdd(&sm.bin.bcnt[b], 1);
            g_slocs[pos] = L;
            g_sidx [pos] = i;
        }
        __syncthreads();
        __threadfence();
        if (tid == 0) atomicExch(&g_bindone, 1);
    }

    // ================= role 1 (bids < MB): pairs (top-9 + box losses) =========
    if (bid < MB) {
        if (tid == 0) {             // waits only for block 0's binning (~3us)
            while (atomicAdd(&g_bindone, 0) == 0) __nanosleep(64);
        }
        __syncthreads();
        __threadfence();

        const int pair = bid * WARPS + warp;
        if (pair < P) {
            float4 gb = gt_boxes[pair];
            const float cx = gb.x, cy = gb.y;
            const int bx = min(NBX - 1, (int)(cx * (float)NBX));
            const int by = min(NBX - 1, (int)(cy * (float)NBX));
            const int bx0 = max(bx - 1, 0), bx1 = min(bx + 1, NBX - 1);
            const int by0 = max(by - 1, 0), by1 = min(by + 1, NBX - 1);

            float dk[KSEL]; int ik[KSEL];
#pragma unroll
            for (int j = 0; j < KSEL; ++j) { dk[j] = INF; ik[j] = 0x7fffffff; }

            for (int yy = by0; yy <= by1; ++yy) {
                int s = g_binOff[yy * NBX + bx0];
                int e = g_binOff[yy * NBX + bx1 + 1];
                for (int i = s + lane; i < e; i += 32) {
                    float2 L = g_slocs[i];
                    float dx = cx - L.x, dy = cy - L.y;
                    insert9(dk, ik, fmaf(dx, dx, dy * dy), g_sidx[i]);
                }
            }
            unsigned long long mykey = warp_merge9(dk, ik, lane);

            // exact coverage certificate: 3x3 bins cover radius rcov around
            // (cx,cy); domain edges extend coverage to infinity (no points
            // outside [0,1]^2). If 9th-best d2 > rcov^2, brute-force exactly.
            const float BW = 1.0f / (float)NBX;
            float rx0 = (bx0 > 0)       ? cx - (float)bx0 * BW        : INF;
            float rx1 = (bx1 < NBX - 1) ? (float)(bx1 + 1) * BW - cx  : INF;
            float ry0 = (by0 > 0)       ? cy - (float)by0 * BW        : INF;
            float ry1 = (by1 < NBX - 1) ? (float)(by1 + 1) * BW - cy  : INF;
            float rcov = fminf(fminf(rx0, rx1), fminf(ry0, ry1));
            unsigned d9b = (unsigned)(__shfl_sync(FULLMASK, mykey, KSEL - 1) >> 32);
            float d9 = __uint_as_float(d9b);
            if (!(d9 <= rcov * rcov)) {      // also catches <9 survivors (INF)
#pragma unroll
                for (int j = 0; j < KSEL; ++j) { dk[j] = INF; ik[j] = 0x7fffffff; }
                for (int n = lane; n < N; n += 32) {
                    float2 L = locs[n];
                    float dx = cx - L.x, dy = cy - L.y;
                    insert9(dk, ik, fmaf(dx, dx, dy * dy), n);
                }
                mykey = warp_merge9(dk, ik, lane);
            }

            const int b = pair / G;
            float l1 = 0.0f, gl = 0.0f, delta = 0.0f;
            if (lane < KSEL) {
                int myN = (int)(mykey & 0xffffffffULL);
                float4 pb = pred_boxes[(long long)b * N + myN];
                l1 = fabsf(pb.x - gb.x) + fabsf(pb.y - gb.y)
                   + fabsf(pb.z - gb.z) + fabsf(pb.w - gb.w);

                float ax0 = pb.x - 0.5f * pb.z, ay0 = pb.y - 0.5f * pb.w;
                float ax1 = pb.x + 0.5f * pb.z, ay1 = pb.y + 0.5f * pb.w;
                float bxx0 = gb.x - 0.5f * gb.z, byy0 = gb.y - 0.5f * gb.w;
                float bxx1 = gb.x + 0.5f * gb.z, byy1 = gb.y + 0.5f * gb.w;

                float area_a = (ax1 - ax0) * (ay1 - ay0);
                float area_b = (bxx1 - bxx0) * (byy1 - byy0);
                float iw = fmaxf(fminf(ax1, bxx1) - fmaxf(ax0, bxx0), 0.0f);
                float ih = fmaxf(fminf(ay1, byy1) - fmaxf(ay0, byy0), 0.0f);
                float inter = iw * ih;
                float uni   = area_a + area_b - inter;
                float iou   = inter / uni;
                float cw = fmaxf(fmaxf(ax1, bxx1) - fminf(ax0, bxx0), 0.0f);
                float ch = fmaxf(fmaxf(ay1, byy1) - fminf(ay0, byy0), 0.0f);
                float areac = cw * ch;
                gl = 1.0f - (iou - (areac - uni) / areac);

                int lbl = gt_labels[pair];
                float x = logits[(long long)(b * N + myN) * C + lbl];
                delta = focal_t1(x) - focal_t0(x);
            }
#pragma unroll
            for (int off = 16; off > 0; off >>= 1) {
                l1    += __shfl_down_sync(FULLMASK, l1,    off);
                gl    += __shfl_down_sync(FULLMASK, gl,    off);
                delta += __shfl_down_sync(FULLMASK, delta, off);
            }
            if (lane == 0) {
                g_part_bbox [pair] = l1;
                g_part_giou [pair] = gl;
                g_part_delta[pair] = delta;
            }
        }
    }

    // ================= role 2 (ALL blocks): focal tile stealing ===============
    {
        const float4* __restrict__ l4 = (const float4*)logits;
        const int itersPerTile = tileUnits / TPB;
        const float4 Z = make_float4(0.f, 0.f, 0.f, 0.f);
        for (;;) {
            __syncthreads();        // protects sm union + stile reuse
            if (tid == 0) stile = atomicAdd(&g_tile, 1);
            __syncthreads();
            const int t = stile;
            if (t >= NT) break;

            const int base = t * tileUnits;
            unsigned long long ACC = 0ULL;    // packed (0.0f, 0.0f)

            int  u = base + tid;
            bool v = (u < n8f);
            float4 a = v ? l4[2 * u]     : Z;
            float4 b = v ? l4[2 * u + 1] : Z;
            for (int k = 1; k < itersPerTile; ++k) {
                int  un = u + TPB;
                bool vn = (un < n8f);
                float4 an = vn ? l4[2 * un]     : Z;   // prefetch next
                float4 bn = vn ? l4[2 * un + 1] : Z;
                if (v) { focal4(a, ACC); focal4(b, ACC); }
                u = un; v = vn; a = an; b = bn;
            }
            if (v) { focal4(a, ACC); focal4(b, ACC); }

            float lo, hi;
            upk2(ACC, lo, hi);
            float acc = 0.75f * (lo + hi);
            if (t == NT - 1 && tid == 0) {   // scalar tail (tile-keyed => deterministic)
                for (int i = n8f * 8; i < total; ++i) acc += focal_t0(logits[i]);
            }
#pragma unroll
            for (int off = 16; off > 0; off >>= 1)
                acc += __shfl_down_sync(FULLMASK, acc, off);
            if (lane == 0) sm.red[warp] = acc;
            __syncthreads();
            if (warp == 0) {
                float vv = (lane < WARPS) ? sm.red[lane] : 0.0f;
#pragma unroll
                for (int off = 4; off > 0; off >>= 1)
                    vv += __shfl_down_sync(FULLMASK, vv, off);
                if (lane == 0) g_part_focal[t] = vv;
            }
        }
    }

    // ================= role 3: last block finalizes ===========================
    __threadfence();
    __syncthreads();
    if (tid == 0) sticket = atomicAdd(&g_ctr, 1);
    __syncthreads();
    if (sticket == (int)gridDim.x - 1) {
        double a0 = 0.0, a1 = 0.0, a2 = 0.0;
        for (int i = tid; i < NT; i += TPB) a0 += (double)g_part_focal[i];
        for (int i = tid; i < P; i += TPB) {
            a0 += (double)g_part_delta[i];
            a1 += (double)g_part_bbox [i];
            a2 += (double)g_part_giou [i];
        }
        sm.dred[0][tid] = a0; sm.dred[1][tid] = a1; sm.dred[2][tid] = a2;
        __syncthreads();
#pragma unroll
        for (int s = 128; s > 0; s >>= 1) {
            if (tid < s) {
                sm.dred[0][tid] += sm.dred[0][tid + s];
                sm.dred[1][tid] += sm.dred[1][tid + s];
                sm.dred[2][tid] += sm.dred[2][tid + s];
            }
            __syncthreads();
        }
        if (tid == 0) {
            out[0] = (float)(sm.dred[0][0] * invBNC);
            out[1] = (float)(sm.dred[1][0] * invBB);
            out[2] = (float)(sm.dred[2][0] * invGI);
            g_ctr     = 0;   // self-reset for next graph replay
            g_tile    = 0;
            g_bindone = 0;
        }
    }
}

// ---------------- launch ----------------------------------------------------
extern "C" void kernel_launch(void* const* d_in, const int* in_sizes, int n_in,
                              void* d_out, int out_size)
{
    const float* logits = (const float*)d_in[0];   // (B,N,C)
    const float* pboxes = (const float*)d_in[1];   // (B,N,4)
    const float* locs   = (const float*)d_in[2];   // (N,2)
    const float* gboxes = (const float*)d_in[3];   // (B,G,4)
    const int*   glabel = (const int*)  d_in[4];   // (B,G)

    const int N = in_sizes[2] / 2;
    const int B = in_sizes[1] / (4 * N);
    const int C = in_sizes[0] / (B * N);
    const int G = in_sizes[4] / B;
    const int P = B * G;

    const int total = in_sizes[0];
    const int n8f   = total / 8;

    // focal tiling (tile-keyed partials; NT must fit g_part_focal)
    int tileUnits = 2048;                      // 8 iterations of 256 threads
    int NT = (n8f + tileUnits - 1) / tileUnits;
    while (NT > 4096) { tileUnits *= 2; NT = (n8f + tileUnits - 1) / tileUnits; }

    const int MB = (P + WARPS - 1) / WARPS;    // 128 pair blocks
    int grid = 6 * 148;                        // 888: fully resident at 6 CTAs/SM
    if (grid < MB + 1) grid = MB + 1;

    double invBNC = 1.0 / ((double)B * (double)N * (double)C);
    double invBB  = 1.0 / ((double)P * (double)KSEL * 4.0);
    double invGI  = 1.0 / ((double)P * (double)KSEL);

    mega_kernel<<<grid, TPB>>>(logits, (const float4*)pboxes,
                               (const float2*)locs, (const float4*)gboxes,
                               glabel, (float*)d_out,
                               B, N, C, G, MB,
                               n8f, total, NT, tileUnits,
                               invBNC, invBB, invGI);
}